// round 1
// baseline (speedup 1.0000x reference)
#include <cuda_runtime.h>

#define NN 100000
#define EE 800000
#define GG 64
#define HH 128
#define FIN 64

// Scratch (allocation-free rule: __device__ globals)
__device__ float g_h[(size_t)NN * HH];     // 51.2 MB
__device__ float g_agg[(size_t)NN * HH];   // 51.2 MB
__device__ float g_dinv[NN];               // deg -> dinv in place
__device__ float g_pool[GG * HH + GG];     // pooled sums + counts

// ---------------------------------------------------------------------------
__global__ void zero_kernel(float* __restrict__ p, int n) {
    int i = blockIdx.x * blockDim.x + threadIdx.x;
    if (i < n) p[i] = 0.0f;
}

__global__ void deg_kernel(const int* __restrict__ ei) {
    int e = blockIdx.x * blockDim.x + threadIdx.x;
    if (e < EE) atomicAdd(&g_dinv[ei[EE + e]], 1.0f);
}

__global__ void dinv_kernel() {
    int i = blockIdx.x * blockDim.x + threadIdx.x;
    if (i < NN) g_dinv[i] = rsqrtf(g_dinv[i] + 1.0f);
}

// ---------------------------------------------------------------------------
// GEMM: Hout[N,128] = act(A + bprev) @ W[K,128]; Agg = Hout * dinv^2 (self loop).
// Block = 256 threads (8 warps), warp owns 4 rows, thread owns 4 output cols.
// In-place safe when A == Agg: each warp reads only the rows it writes,
// reads happen before writes within the warp.
template <int K, bool ACT>
__global__ void gemm_kernel(const float* __restrict__ A,
                            const float* __restrict__ bprev,
                            const float* __restrict__ W,
                            float* __restrict__ Hout,
                            float* __restrict__ Agg) {
    __shared__ float4 Wsh[64 * 32];  // 64 k-rows x 128 cols = 32 KB
    const int tid = threadIdx.x;
    const int lane = tid & 31;
    const int warp = tid >> 5;
    const int row0 = blockIdx.x * 32 + warp * 4;

    // Preload A rows into registers (K/32 values per row per lane)
    float a[4][K / 32];
#pragma unroll
    for (int r = 0; r < 4; r++) {
        const int row = row0 + r;
        const float* Ar = A + (size_t)row * K;
#pragma unroll
        for (int i = 0; i < K / 32; i++) {
            const int k = lane + 32 * i;
            float v = (row < NN) ? Ar[k] : 0.0f;
            if (ACT) v = fmaxf(v + bprev[k], 0.0f);
            a[r][i] = v;
        }
    }

    float4 acc[4];
#pragma unroll
    for (int r = 0; r < 4; r++) acc[r] = make_float4(0.f, 0.f, 0.f, 0.f);

#pragma unroll
    for (int ph = 0; ph < K / 64; ph++) {
        __syncthreads();
        const float4* Wg = (const float4*)(W + (size_t)ph * 64 * HH);
        for (int i = tid; i < 64 * 32; i += 256) Wsh[i] = Wg[i];
        __syncthreads();
#pragma unroll
        for (int half = 0; half < 2; half++) {
            const int reg = ph * 2 + half;  // compile-time register index
#pragma unroll 8
            for (int ks = 0; ks < 32; ks++) {
                const float4 w = Wsh[(half * 32 + ks) * 32 + lane];
#pragma unroll
                for (int r = 0; r < 4; r++) {
                    const float ak = __shfl_sync(0xffffffffu, a[r][reg], ks);
                    acc[r].x += ak * w.x;
                    acc[r].y += ak * w.y;
                    acc[r].z += ak * w.z;
                    acc[r].w += ak * w.w;
                }
            }
        }
    }

#pragma unroll
    for (int r = 0; r < 4; r++) {
        const int row = row0 + r;
        if (row < NN) {
            const float d = g_dinv[row];
            const float s = d * d;
            ((float4*)(Hout + (size_t)row * HH))[lane] = acc[r];
            float4 ag = make_float4(acc[r].x * s, acc[r].y * s, acc[r].z * s, acc[r].w * s);
            ((float4*)(Agg + (size_t)row * HH))[lane] = ag;
        }
    }
}

// ---------------------------------------------------------------------------
// Edge scatter: one warp per edge; lane handles 4 features via vectorized red.
__global__ void edge_kernel(const int* __restrict__ ei,
                            const float* __restrict__ h,
                            float* __restrict__ agg) {
    const int e = blockIdx.x * 8 + (threadIdx.x >> 5);
    if (e >= EE) return;
    const int lane = threadIdx.x & 31;
    const int src = ei[e];
    const int dst = ei[EE + e];
    const float norm = g_dinv[src] * g_dinv[dst];
    float4 v = ((const float4*)(h + (size_t)src * HH))[lane];
    float* p = agg + (size_t)dst * HH + lane * 4;
    asm volatile("red.global.add.v4.f32 [%0], {%1, %2, %3, %4};" ::"l"(p),
                 "f"(v.x * norm), "f"(v.y * norm), "f"(v.z * norm), "f"(v.w * norm)
                 : "memory");
}

// ---------------------------------------------------------------------------
// Pool: sum (agg3 + b3) per graph + node counts.
__global__ void pool_kernel(const float* __restrict__ agg,
                            const float* __restrict__ b3,
                            const int* __restrict__ batch) {
    const int i = blockIdx.x * blockDim.x + threadIdx.x;
    if (i >= NN * 32) return;
    const int node = i >> 5;
    const int q = i & 31;
    const int g = batch[node];
    float4 v = ((const float4*)agg)[i];
    const float4 bb = ((const float4*)b3)[q];
    v.x += bb.x; v.y += bb.y; v.z += bb.z; v.w += bb.w;
    float* p = g_pool + g * HH + q * 4;
    asm volatile("red.global.add.v4.f32 [%0], {%1, %2, %3, %4};" ::"l"(p),
                 "f"(v.x), "f"(v.y), "f"(v.z), "f"(v.w)
                 : "memory");
    if (q == 0) atomicAdd(&g_pool[GG * HH + g], 1.0f);
}

// ---------------------------------------------------------------------------
// Final MLP: one block per graph.
__global__ void mlp_kernel(const float* __restrict__ fw1, const float* __restrict__ fb1,
                           const float* __restrict__ fw2, const float* __restrict__ fb2,
                           float* __restrict__ out) {
    const int g = blockIdx.x;
    const int j = threadIdx.x;  // 128 threads
    __shared__ float p[HH];
    __shared__ float z[HH];
    const float c = fmaxf(g_pool[GG * HH + g], 1.0f);
    p[j] = g_pool[g * HH + j] / c;
    __syncthreads();
    float acc = fb1[j];
#pragma unroll 8
    for (int k = 0; k < HH; k++) acc += p[k] * fw1[k * HH + j];
    z[j] = fmaxf(acc, 0.0f);
    __syncthreads();
    if (j < 4) {
        float o = fb2[j];
#pragma unroll 8
        for (int k = 0; k < HH; k++) o += z[k] * fw2[k * 4 + j];
        out[g * 4 + j] = o;
    }
}

// ---------------------------------------------------------------------------
extern "C" void kernel_launch(void* const* d_in, const int* in_sizes, int n_in,
                              void* d_out, int out_size) {
    const float* x   = (const float*)d_in[0];
    const float* W1  = (const float*)d_in[1];
    const float* b1  = (const float*)d_in[2];
    const float* W2  = (const float*)d_in[3];
    const float* b2  = (const float*)d_in[4];
    const float* W3  = (const float*)d_in[5];
    const float* b3  = (const float*)d_in[6];
    const float* fw1 = (const float*)d_in[7];
    const float* fb1 = (const float*)d_in[8];
    const float* fw2 = (const float*)d_in[9];
    const float* fb2 = (const float*)d_in[10];
    const int*   ei  = (const int*)d_in[11];
    const int*   bat = (const int*)d_in[12];
    float* out = (float*)d_out;

    float *dh, *dagg, *ddinv, *dpool;
    cudaGetSymbolAddress((void**)&dh, g_h);
    cudaGetSymbolAddress((void**)&dagg, g_agg);
    cudaGetSymbolAddress((void**)&ddinv, g_dinv);
    cudaGetSymbolAddress((void**)&dpool, g_pool);

    // Degree -> dinv
    zero_kernel<<<(NN + 255) / 256, 256>>>(ddinv, NN);
    deg_kernel<<<(EE + 255) / 256, 256>>>(ei);
    dinv_kernel<<<(NN + 255) / 256, 256>>>();

    const int GEMM_GRID = (NN + 31) / 32;  // 3125
    const int EDGE_GRID = (EE + 7) / 8;    // 100000

    // Layer 1: h = x @ W1; agg = self + scatter
    gemm_kernel<FIN, false><<<GEMM_GRID, 256>>>(x, nullptr, W1, dh, dagg);
    edge_kernel<<<EDGE_GRID, 256>>>(ei, dh, dagg);

    // Layer 2: input relu(agg + b1) fused into GEMM A-load (in-place safe)
    gemm_kernel<HH, true><<<GEMM_GRID, 256>>>(dagg, b1, W2, dh, dagg);
    edge_kernel<<<EDGE_GRID, 256>>>(ei, dh, dagg);

    // Layer 3
    gemm_kernel<HH, true><<<GEMM_GRID, 256>>>(dagg, b2, W3, dh, dagg);
    edge_kernel<<<EDGE_GRID, 256>>>(ei, dh, dagg);

    // Pool + MLP head
    zero_kernel<<<(GG * HH + GG + 255) / 256, 256>>>(dpool, GG * HH + GG);
    pool_kernel<<<(NN * 32 + 255) / 256, 256>>>(dagg, b3, bat);
    mlp_kernel<<<GG, HH>>>(fw1, fb1, fw2, fb2, out);
}

// round 2
// speedup vs baseline: 1.9143x; 1.9143x over previous
#include <cuda_runtime.h>

#define NN 100000
#define EE 800000
#define GG 64
#define HH 128
#define FIN 64
#define NBLK ((NN + 1023) / 1024)   // scan blocks = 98

// Scratch (allocation-free rule: __device__ globals)
__device__ __align__(16) float g_u[(size_t)NN * HH];   // aggregated input to GEMM
__device__ __align__(16) float g_z[(size_t)NN * HH];   // GEMM output / activation
__device__ float g_dinv[NN];
__device__ int   g_cnt[NN];
__device__ int   g_off[NN + 1];
__device__ int   g_cur[NN];
__device__ int   g_csr[EE];
__device__ int   g_bsum[128];
__device__ __align__(16) float g_pool[GG * HH + GG];

// ---------------------------------------------------------------------------
__global__ void zero_int_kernel(int* __restrict__ p, int n) {
    int i = blockIdx.x * blockDim.x + threadIdx.x;
    if (i < n) p[i] = 0;
}
__global__ void zero_f_kernel(float* __restrict__ p, int n) {
    int i = blockIdx.x * blockDim.x + threadIdx.x;
    if (i < n) p[i] = 0.0f;
}

__global__ void hist_kernel(const int* __restrict__ ei) {
    int e = blockIdx.x * blockDim.x + threadIdx.x;
    if (e < EE) atomicAdd(&g_cnt[ei[EE + e]], 1);
}

// Block-level scan (1024 elems / block, 256 threads x 4). Also computes dinv.
__global__ void scan1_kernel() {
    __shared__ int ssum[256];
    const int tid = threadIdx.x;
    const int base = blockIdx.x * 1024 + tid * 4;
    int v[4];
#pragma unroll
    for (int j = 0; j < 4; j++) {
        int idx = base + j;
        v[j] = (idx < NN) ? g_cnt[idx] : 0;
        if (idx < NN) g_dinv[idx] = rsqrtf((float)v[j] + 1.0f);
    }
    int s = v[0] + v[1] + v[2] + v[3];
    ssum[tid] = s;
    __syncthreads();
    for (int d = 1; d < 256; d <<= 1) {
        int t = (tid >= d) ? ssum[tid - d] : 0;
        __syncthreads();
        ssum[tid] += t;
        __syncthreads();
    }
    int run = ssum[tid] - s;  // exclusive prefix within block
#pragma unroll
    for (int j = 0; j < 4; j++) {
        int idx = base + j;
        if (idx < NN) g_off[idx] = run;
        run += v[j];
    }
    if (tid == 255) g_bsum[blockIdx.x] = ssum[255];
}

__global__ void scan2_kernel() {
    __shared__ int s[128];
    const int tid = threadIdx.x;
    int v = (tid < NBLK) ? g_bsum[tid] : 0;
    s[tid] = v;
    __syncthreads();
    for (int d = 1; d < 128; d <<= 1) {
        int t = (tid >= d) ? s[tid - d] : 0;
        __syncthreads();
        s[tid] += t;
        __syncthreads();
    }
    g_bsum[tid] = s[tid] - v;  // exclusive
}

__global__ void scan3_kernel() {
    int i = blockIdx.x * blockDim.x + threadIdx.x;
    if (i < NN) {
        int off = g_off[i] + g_bsum[i >> 10];
        g_off[i] = off;
        g_cur[i] = off;
    }
    if (i == 0) g_off[NN] = EE;
}

__global__ void scatter_kernel(const int* __restrict__ ei) {
    int e = blockIdx.x * blockDim.x + threadIdx.x;
    if (e >= EE) return;
    int src = ei[e];
    int dst = ei[EE + e];
    int pos = atomicAdd(&g_cur[dst], 1);
    g_csr[pos] = src;
}

// ---------------------------------------------------------------------------
// Aggregation u = A_hat * z  (normalized adjacency with self loops), CSR-based,
// atomic-free. DIM/4 threads cooperate per node, each owning a float4 slot.
template <int DIM>
__global__ void agg_kernel(const float* __restrict__ z, float* __restrict__ u) {
    constexpr int GPN = DIM / 4;            // 16 or 32 threads per node
    constexpr int SH = (DIM == 64) ? 4 : 5;
    const int gt = blockIdx.x * 256 + threadIdx.x;
    const int node = gt >> SH;
    if (node >= NN) return;
    const int q = gt & (GPN - 1);
    const float dd = g_dinv[node];
    const int s = g_off[node], e = g_off[node + 1];
    const float4* Z = (const float4*)z;
    float4 v0 = Z[(size_t)node * GPN + q];
    float ax = dd * v0.x, ay = dd * v0.y, az = dd * v0.z, aw = dd * v0.w;
    int i = s;
    for (; i + 1 < e; i += 2) {
        int s0 = g_csr[i], s1 = g_csr[i + 1];
        float d0 = g_dinv[s0], d1 = g_dinv[s1];
        float4 a = Z[(size_t)s0 * GPN + q];
        float4 b = Z[(size_t)s1 * GPN + q];
        ax += d0 * a.x + d1 * b.x;
        ay += d0 * a.y + d1 * b.y;
        az += d0 * a.z + d1 * b.z;
        aw += d0 * a.w + d1 * b.w;
    }
    if (i < e) {
        int s0 = g_csr[i];
        float d0 = g_dinv[s0];
        float4 a = Z[(size_t)s0 * GPN + q];
        ax += d0 * a.x; ay += d0 * a.y; az += d0 * a.z; aw += d0 * a.w;
    }
    ((float4*)u)[(size_t)node * GPN + q] = make_float4(dd * ax, dd * ay, dd * az, dd * aw);
}

// ---------------------------------------------------------------------------
// GEMM: Z[N,128] = act(A[N,K] @ W[K,128] + b). 128 threads, 64x128 tile,
// 8x8 outputs per thread. POOL variant reduces straight into g_pool (no store).
template <int K, bool RELU, bool POOL>
__global__ void __launch_bounds__(128) gemm_kernel(const float* __restrict__ A,
                                                   const float* __restrict__ W,
                                                   const float* __restrict__ bias,
                                                   float* __restrict__ Z,
                                                   const int* __restrict__ batch) {
    __shared__ float Ash[32 * 65];   // transposed A chunk, pad 65
    __shared__ float Wsh[32 * 128];
    const int tid = threadIdx.x;
    const int lane = tid & 31;
    const int warp = tid >> 5;
    const int r0 = warp * 16 + (lane >> 4) * 8;  // 8 rows
    const int c0 = (lane & 15) * 8;              // 8 cols
    const int blockRow = blockIdx.x * 64;

    float4 acc[8][2];
#pragma unroll
    for (int i = 0; i < 8; i++) {
        acc[i][0] = make_float4(0.f, 0.f, 0.f, 0.f);
        acc[i][1] = make_float4(0.f, 0.f, 0.f, 0.f);
    }

    for (int kc = 0; kc < K; kc += 32) {
        // W chunk: rows kc..kc+31, all 128 cols (contiguous)
        const float4* Wg = (const float4*)(W + (size_t)kc * HH);
        float4* Wsh4 = (float4*)Wsh;
#pragma unroll
        for (int i = tid; i < 1024; i += 128) Wsh4[i] = Wg[i];
        // A chunk transposed: Ash[k][row], row in 0..63
#pragma unroll
        for (int i = 0; i < 4; i++) {
            int idx = tid * 4 + i;
            int row = idx >> 3;
            int q = idx & 7;
            int grow = blockRow + row;
            float4 av = (grow < NN)
                ? ((const float4*)(A + (size_t)grow * K + kc))[q]
                : make_float4(0.f, 0.f, 0.f, 0.f);
            Ash[(q * 4 + 0) * 65 + row] = av.x;
            Ash[(q * 4 + 1) * 65 + row] = av.y;
            Ash[(q * 4 + 2) * 65 + row] = av.z;
            Ash[(q * 4 + 3) * 65 + row] = av.w;
        }
        __syncthreads();
#pragma unroll 8
        for (int k = 0; k < 32; k++) {
            float4 w0 = ((const float4*)Wsh)[k * 32 + (c0 >> 2)];
            float4 w1 = ((const float4*)Wsh)[k * 32 + (c0 >> 2) + 1];
#pragma unroll
            for (int i = 0; i < 8; i++) {
                float a = Ash[k * 65 + r0 + i];
                acc[i][0].x += a * w0.x;
                acc[i][0].y += a * w0.y;
                acc[i][0].z += a * w0.z;
                acc[i][0].w += a * w0.w;
                acc[i][1].x += a * w1.x;
                acc[i][1].y += a * w1.y;
                acc[i][1].z += a * w1.z;
                acc[i][1].w += a * w1.w;
            }
        }
        __syncthreads();
    }

    if (!POOL) {
        const float4 b0 = ((const float4*)bias)[c0 >> 2];
        const float4 b1 = ((const float4*)bias)[(c0 >> 2) + 1];
#pragma unroll
        for (int i = 0; i < 8; i++) {
            int row = blockRow + r0 + i;
            if (row >= NN) continue;
            float4 o0 = make_float4(acc[i][0].x + b0.x, acc[i][0].y + b0.y,
                                    acc[i][0].z + b0.z, acc[i][0].w + b0.w);
            float4 o1 = make_float4(acc[i][1].x + b1.x, acc[i][1].y + b1.y,
                                    acc[i][1].z + b1.z, acc[i][1].w + b1.w);
            if (RELU) {
                o0.x = fmaxf(o0.x, 0.f); o0.y = fmaxf(o0.y, 0.f);
                o0.z = fmaxf(o0.z, 0.f); o0.w = fmaxf(o0.w, 0.f);
                o1.x = fmaxf(o1.x, 0.f); o1.y = fmaxf(o1.y, 0.f);
                o1.z = fmaxf(o1.z, 0.f); o1.w = fmaxf(o1.w, 0.f);
            }
            float4* Zr = (float4*)(Z + (size_t)row * HH + c0);
            Zr[0] = o0;
            Zr[1] = o1;
        }
    } else {
        // Reduce straight into pool[batch[row]] (bias folded into MLP head).
#pragma unroll
        for (int i = 0; i < 8; i++) {
            int row = blockRow + r0 + i;
            if (row >= NN) continue;
            int g = batch[row];
            float* p = g_pool + g * HH + c0;
            asm volatile("red.global.add.v4.f32 [%0], {%1, %2, %3, %4};" ::"l"(p),
                         "f"(acc[i][0].x), "f"(acc[i][0].y), "f"(acc[i][0].z),
                         "f"(acc[i][0].w) : "memory");
            asm volatile("red.global.add.v4.f32 [%0], {%1, %2, %3, %4};" ::"l"(p + 4),
                         "f"(acc[i][1].x), "f"(acc[i][1].y), "f"(acc[i][1].z),
                         "f"(acc[i][1].w) : "memory");
        }
    }
}

// ---------------------------------------------------------------------------
__global__ void count_kernel(const int* __restrict__ batch) {
    int i = blockIdx.x * blockDim.x + threadIdx.x;
    if (i < NN) atomicAdd(&g_pool[GG * HH + batch[i]], 1.0f);
}

// Final MLP head: one block per graph. p = pool/cnt + b3.
__global__ void mlp_kernel(const float* __restrict__ b3,
                           const float* __restrict__ fw1, const float* __restrict__ fb1,
                           const float* __restrict__ fw2, const float* __restrict__ fb2,
                           float* __restrict__ out) {
    const int g = blockIdx.x;
    const int j = threadIdx.x;  // 128
    __shared__ float p[HH];
    __shared__ float z[HH];
    const float c = fmaxf(g_pool[GG * HH + g], 1.0f);
    p[j] = g_pool[g * HH + j] / c + b3[j];
    __syncthreads();
    float acc = fb1[j];
#pragma unroll 8
    for (int k = 0; k < HH; k++) acc += p[k] * fw1[k * HH + j];
    z[j] = fmaxf(acc, 0.0f);
    __syncthreads();
    if (j < 4) {
        float o = fb2[j];
#pragma unroll 8
        for (int k = 0; k < HH; k++) o += z[k] * fw2[k * 4 + j];
        out[g * 4 + j] = o;
    }
}

// ---------------------------------------------------------------------------
extern "C" void kernel_launch(void* const* d_in, const int* in_sizes, int n_in,
                              void* d_out, int out_size) {
    const float* x   = (const float*)d_in[0];
    const float* W1  = (const float*)d_in[1];
    const float* b1  = (const float*)d_in[2];
    const float* W2  = (const float*)d_in[3];
    const float* b2  = (const float*)d_in[4];
    const float* W3  = (const float*)d_in[5];
    const float* b3  = (const float*)d_in[6];
    const float* fw1 = (const float*)d_in[7];
    const float* fb1 = (const float*)d_in[8];
    const float* fw2 = (const float*)d_in[9];
    const float* fb2 = (const float*)d_in[10];
    const int*   ei  = (const int*)d_in[11];
    const int*   bat = (const int*)d_in[12];
    float* out = (float*)d_out;

    float *du, *dz, *dpool;
    int *dcnt;
    cudaGetSymbolAddress((void**)&du, g_u);
    cudaGetSymbolAddress((void**)&dz, g_z);
    cudaGetSymbolAddress((void**)&dpool, g_pool);
    cudaGetSymbolAddress((void**)&dcnt, g_cnt);

    // --- CSR build (also yields degrees -> dinv) ---
    zero_int_kernel<<<(NN + 255) / 256, 256>>>(dcnt, NN);
    zero_f_kernel<<<(GG * HH + GG + 255) / 256, 256>>>(dpool, GG * HH + GG);
    hist_kernel<<<(EE + 255) / 256, 256>>>(ei);
    scan1_kernel<<<NBLK, 256>>>();
    scan2_kernel<<<1, 128>>>();
    scan3_kernel<<<(NN + 255) / 256, 256>>>();
    scatter_kernel<<<(EE + 255) / 256, 256>>>(ei);

    const int GEMM_GRID = (NN + 63) / 64;  // 1563

    // Layer 1: u = A_hat x (64-dim), z = relu(u W1 + b1)
    agg_kernel<FIN><<<(NN * 16 + 255) / 256, 256>>>(x, du);
    gemm_kernel<FIN, true, false><<<GEMM_GRID, 128>>>(du, W1, b1, dz, nullptr);

    // Layer 2
    agg_kernel<HH><<<(NN * 32 + 255) / 256, 256>>>(dz, du);
    gemm_kernel<HH, true, false><<<GEMM_GRID, 128>>>(du, W2, b2, dz, nullptr);

    // Layer 3: GEMM reduces directly into pool (bias b3 folded into MLP)
    agg_kernel<HH><<<(NN * 32 + 255) / 256, 256>>>(dz, du);
    gemm_kernel<HH, false, true><<<GEMM_GRID, 128>>>(du, W3, nullptr, nullptr, bat);

    count_kernel<<<(NN + 255) / 256, 256>>>(bat);
    mlp_kernel<<<GG, HH>>>(b3, fw1, fb1, fw2, fb2, out);
}